// round 8
// baseline (speedup 1.0000x reference)
#include <cuda_runtime.h>
#include <cuda_bf16.h>
#include <stdint.h>

#define FFEAT   32
#define DDIM    64
#define P_PAIRS 496
#define FD      (FFEAT * DDIM)   // 2048
#define MT      128
#define THREADS 128

#define APITCH 72                  // bf16 per row = 144 B
#define ROWB   (APITCH * 2)

// smem layout (aliased):
//  [0,36864)      A_hi/A_lo during init  -> reused as W tile buffers 0/1 in loop
//  [36864,69632)  raw W double buffer (cp.async dst)
//  [69632,87040)  per-warp f32 staging
#define SM_AH    0
#define SM_AL    18432
#define TILE_HI(b) ((b) * 18432)
#define TILE_LO(b) ((b) * 18432 + 9216)
#define SM_RAW   36864
#define RAWBUF(b) (SM_RAW + (b) * 16384)
#define SM_ST    69632
#define STPITCH  68
#define ST_WARP  (16 * STPITCH * 4)            // 4352 B
#define SMEM_BYTES (SM_ST + 4 * ST_WARP)       // 87040

static __device__ __forceinline__ uint32_t smem_u32(const void* p) {
    uint32_t a;
    asm("{ .reg .u64 t; cvta.to.shared.u64 t, %1; cvt.u32.u64 %0, t; }" : "=r"(a) : "l"(p));
    return a;
}
static __device__ __forceinline__ uint32_t packbf(float lo_e, float hi_e) {
    uint32_t r;
    asm("cvt.rn.bf16x2.f32 %0, %1, %2;" : "=r"(r) : "f"(hi_e), "f"(lo_e));
    return r;
}
static __device__ __forceinline__ float bf_rt(float x) {
    return __bfloat162float(__float2bfloat16(x));
}

#define LDSM_X4(r, addr)                                                     \
    asm volatile("ldmatrix.sync.aligned.m8n8.x4.shared.b16 {%0,%1,%2,%3}, [%4];" \
        : "=r"((r)[0]), "=r"((r)[1]), "=r"((r)[2]), "=r"((r)[3]) : "r"(addr))
#define LDSM_X4_T(r, addr)                                                   \
    asm volatile("ldmatrix.sync.aligned.m8n8.x4.trans.shared.b16 {%0,%1,%2,%3}, [%4];" \
        : "=r"((r)[0]), "=r"((r)[1]), "=r"((r)[2]), "=r"((r)[3]) : "r"(addr))
#define MMA16816(d, a, b)                                                    \
    asm volatile("mma.sync.aligned.m16n8k16.row.col.f32.bf16.bf16.f32 "      \
        "{%0,%1,%2,%3},{%4,%5,%6,%7},{%8,%9},{%0,%1,%2,%3};"                 \
        : "+f"((d)[0]), "+f"((d)[1]), "+f"((d)[2]), "+f"((d)[3])             \
        : "r"((a)[0]), "r"((a)[1]), "r"((a)[2]), "r"((a)[3]),                \
          "r"((b)[0]), "r"((b)[1]))

#define CP_ASYNC16(sm, gm) \
    asm volatile("cp.async.cg.shared.global [%0], [%1], 16;" :: "r"(sm), "l"(gm) : "memory")
#define CP_COMMIT()  asm volatile("cp.async.commit_group;" ::: "memory")
#define CP_WAIT1()   asm volatile("cp.async.wait_group 1;" ::: "memory")
#define CP_WAIT0()   asm volatile("cp.async.wait_group 0;" ::: "memory")

static __device__ __forceinline__ void w_cpasync(uint32_t sb, int b, int tid,
                                                 const float* __restrict__ W, int p) {
    const char* wg = (const char*)(W + (size_t)p * DDIM * DDIM);
    #pragma unroll
    for (int t = 0; t < 8; t++) {
        const int idx4 = tid + (t << 7);
        CP_ASYNC16(sb + RAWBUF(b) + idx4 * 16, wg + idx4 * 16);
    }
    CP_COMMIT();
}
// convert own raw bytes (buf b) -> bf16 hi/lo tiles (buf b); no cross-thread deps
static __device__ __forceinline__ void w_convert(char* smem, int b, int tid) {
    #pragma unroll
    for (int t = 0; t < 8; t++) {
        const int idx4 = tid + (t << 7);
        float4 v = *(const float4*)(smem + RAWBUF(b) + idx4 * 16);
        const int k  = idx4 >> 4;
        const int e4 = (idx4 & 15) << 2;
        const uint32_t off = (uint32_t)(k * ROWB + e4 * 2);
        *(uint2*)(smem + TILE_HI(b) + off) =
            make_uint2(packbf(v.x, v.y), packbf(v.z, v.w));
        *(uint2*)(smem + TILE_LO(b) + off) =
            make_uint2(packbf(v.x - bf_rt(v.x), v.y - bf_rt(v.y)),
                       packbf(v.z - bf_rt(v.z), v.w - bf_rt(v.w)));
    }
}

__global__ void __launch_bounds__(THREADS, 2)
bilin_hmma6(const float* __restrict__ X,   // [B, 32, 64]
            const float* __restrict__ W,   // [496, 64, 64]
            float* __restrict__ out)       // [B, 496, 64]
{
    extern __shared__ char smem[];
    const uint32_t sb  = smem_u32(smem);
    const int tid  = threadIdx.x;
    const int wid  = tid >> 5;
    const int lane = tid & 31;
    const int i    = blockIdx.y;
    const int b0   = blockIdx.x * MT;
    const int j0   = i + 1;
    const int pbase = i * (63 - i) / 2 - i - 1;   // p = pbase + j

    // prime W pipeline for first j
    w_cpasync(sb, 0, tid, W, pbase + j0);

    // ---- convert A = X[b0:b0+128, i, :] to bf16 hi/lo smem ----
    {
        const int m = tid;
        const float4* xr = (const float4*)(X + (size_t)(b0 + m) * FD + i * DDIM);
        char* ahp = smem + SM_AH + m * ROWB;
        char* alp = smem + SM_AL + m * ROWB;
        #pragma unroll
        for (int q = 0; q < 16; q++) {
            float4 v = xr[q];
            *(uint2*)(ahp + q * 8) = make_uint2(packbf(v.x, v.y), packbf(v.z, v.w));
            *(uint2*)(alp + q * 8) =
                make_uint2(packbf(v.x - bf_rt(v.x), v.y - bf_rt(v.y)),
                           packbf(v.z - bf_rt(v.z), v.w - bf_rt(v.w)));
        }
    }
    __syncthreads();

    // ---- A fragments in registers (warp owns 32 rows) ----
    uint32_t ah[2][4][4], al[2][4][4];
    {
        const int r16 = lane & 15;
        const int h16 = lane >> 4;
        #pragma unroll
        for (int mt = 0; mt < 2; mt++) {
            const int m = wid * 32 + mt * 16 + r16;
            #pragma unroll
            for (int kt = 0; kt < 4; kt++) {
                const uint32_t off = (uint32_t)(m * ROWB + kt * 32 + h16 * 16);
                LDSM_X4(ah[mt][kt], sb + SM_AH + off);
                LDSM_X4(al[mt][kt], sb + SM_AL + off);
            }
        }
    }
    __syncthreads();   // A region now dead -> safe to reuse as W tile buffers

    int buf = 0;
    for (int j = j0; j < FFEAT; j++, buf ^= 1) {
        const int p = pbase + j;

        // prefetch next W; current one landed an iteration ago
        if (j + 1 < FFEAT) {
            w_cpasync(sb, buf ^ 1, tid, W, p + 1);
            CP_WAIT1();
        } else {
            CP_WAIT0();
        }
        w_convert(smem, buf, tid);
        __syncthreads();   // converted tiles[buf] visible to all warps

        // ---- MMA: D = Xh Wh + Xl Wh + Xh Wl ----
        float acc[2][8][4];
        #pragma unroll
        for (int mt = 0; mt < 2; mt++)
            #pragma unroll
            for (int nt = 0; nt < 8; nt++)
                #pragma unroll
                for (int c = 0; c < 4; c++) acc[mt][nt][c] = 0.f;

        const int kr = lane & 15;
        const int nh = lane >> 4;
        #pragma unroll
        for (int kt = 0; kt < 4; kt++) {
            uint32_t bh[4][4], bl[4][4];
            #pragma unroll
            for (int nb = 0; nb < 4; nb++) {
                const uint32_t off = (uint32_t)((kt * 16 + kr) * ROWB
                                                + nb * 32 + nh * 16);
                LDSM_X4_T(bh[nb], sb + TILE_HI(buf) + off);
                LDSM_X4_T(bl[nb], sb + TILE_LO(buf) + off);
            }
            #pragma unroll
            for (int mt = 0; mt < 2; mt++)
                #pragma unroll
                for (int nb = 0; nb < 4; nb++) {
                    MMA16816(acc[mt][2 * nb + 0], ah[mt][kt], bh[nb] + 0);
                    MMA16816(acc[mt][2 * nb + 1], ah[mt][kt], bh[nb] + 2);
                }
            #pragma unroll
            for (int mt = 0; mt < 2; mt++)
                #pragma unroll
                for (int nb = 0; nb < 4; nb++) {
                    MMA16816(acc[mt][2 * nb + 0], al[mt][kt], bh[nb] + 0);
                    MMA16816(acc[mt][2 * nb + 1], al[mt][kt], bh[nb] + 2);
                }
            #pragma unroll
            for (int mt = 0; mt < 2; mt++)
                #pragma unroll
                for (int nb = 0; nb < 4; nb++) {
                    MMA16816(acc[mt][2 * nb + 0], ah[mt][kt], bl[nb] + 0);
                    MMA16816(acc[mt][2 * nb + 1], ah[mt][kt], bl[nb] + 2);
                }
        }

        // ---- epilogue: stage D half-tile in smem, then coalesced xj/out ----
        {
            char* stw = smem + SM_ST + wid * ST_WARP;
            const int tr = lane >> 2;
            const int tc = (lane & 3) * 2;
            const int r2 = lane >> 4;
            const int c4 = (lane & 15) * 4;
            #pragma unroll
            for (int mt = 0; mt < 2; mt++) {
                __syncwarp();
                #pragma unroll
                for (int nt = 0; nt < 8; nt++) {
                    *(float2*)(stw + (tr * STPITCH + nt * 8 + tc) * 4) =
                        make_float2(acc[mt][nt][0], acc[mt][nt][1]);
                    *(float2*)(stw + ((tr + 8) * STPITCH + nt * 8 + tc) * 4) =
                        make_float2(acc[mt][nt][2], acc[mt][nt][3]);
                }
                __syncwarp();
                #pragma unroll
                for (int s2 = 0; s2 < 8; s2++) {
                    const int r  = s2 * 2 + r2;
                    const int m0 = b0 + wid * 32 + mt * 16 + r;
                    float4 d  = *(const float4*)(stw + (r * STPITCH + c4) * 4);
                    float4 xv = *(const float4*)(X + (size_t)m0 * FD + j * DDIM + c4);
                    float4 o  = make_float4(d.x * xv.x, d.y * xv.y,
                                            d.z * xv.z, d.w * xv.w);
                    *(float4*)(out + ((size_t)m0 * P_PAIRS + p) * DDIM + c4) = o;
                }
            }
        }
    }
}

extern "C" void kernel_launch(void* const* d_in, const int* in_sizes, int n_in,
                              void* d_out, int out_size) {
    const float* X = (const float*)d_in[0];
    const float* W = (const float*)d_in[1];
    float* out = (float*)d_out;

    const int B = in_sizes[0] / FD;   // 4096

    cudaFuncSetAttribute(bilin_hmma6, cudaFuncAttributeMaxDynamicSharedMemorySize, SMEM_BYTES);

    dim3 grid(B / MT, FFEAT - 1);
    bilin_hmma6<<<grid, THREADS, SMEM_BYTES>>>(X, W, out);
}

// round 9
// speedup vs baseline: 1.1467x; 1.1467x over previous
#include <cuda_runtime.h>
#include <cuda_bf16.h>
#include <stdint.h>

#define FFEAT   32
#define DDIM    64
#define P_PAIRS 496
#define FD      (FFEAT * DDIM)   // 2048
#define MT      128
#define THREADS 128

// smem: A_hi[128][72]bf16, A_lo, W_hi[64][72]bf16, W_lo, staging[4][16][68]f32
#define APITCH 72
#define ROWB   (APITCH * 2)
#define SM_AH  0
#define SM_AL  (SM_AH + MT * ROWB)            // 18432
#define SM_WH  (SM_AL + MT * ROWB)            // 36864
#define SM_WL  (SM_WH + DDIM * ROWB)          // 46080
#define SM_ST  (SM_WL + DDIM * ROWB)          // 55296
#define STPITCH 68
#define ST_WARP (16 * STPITCH * 4)             // 4352 B
#define SMEM_BYTES (SM_ST + 4 * ST_WARP)       // 72704  (3 CTAs: 218 KB <= 228)

static __device__ __forceinline__ uint32_t smem_u32(const void* p) {
    uint32_t a;
    asm("{ .reg .u64 t; cvta.to.shared.u64 t, %1; cvt.u32.u64 %0, t; }" : "=r"(a) : "l"(p));
    return a;
}
static __device__ __forceinline__ uint32_t packbf(float lo_e, float hi_e) {
    uint32_t r;
    asm("cvt.rn.bf16x2.f32 %0, %1, %2;" : "=r"(r) : "f"(hi_e), "f"(lo_e));
    return r;
}
static __device__ __forceinline__ float bf_rt(float x) {
    return __bfloat162float(__float2bfloat16(x));
}

#define LDSM_X4(r, addr)                                                     \
    asm volatile("ldmatrix.sync.aligned.m8n8.x4.shared.b16 {%0,%1,%2,%3}, [%4];" \
        : "=r"((r)[0]), "=r"((r)[1]), "=r"((r)[2]), "=r"((r)[3]) : "r"(addr))
#define LDSM_X4_T(r, addr)                                                   \
    asm volatile("ldmatrix.sync.aligned.m8n8.x4.trans.shared.b16 {%0,%1,%2,%3}, [%4];" \
        : "=r"((r)[0]), "=r"((r)[1]), "=r"((r)[2]), "=r"((r)[3]) : "r"(addr))
#define MMA16816(d, a, b)                                                    \
    asm volatile("mma.sync.aligned.m16n8k16.row.col.f32.bf16.bf16.f32 "      \
        "{%0,%1,%2,%3},{%4,%5,%6,%7},{%8,%9},{%0,%1,%2,%3};"                 \
        : "+f"((d)[0]), "+f"((d)[1]), "+f"((d)[2]), "+f"((d)[3])             \
        : "r"((a)[0]), "r"((a)[1]), "r"((a)[2]), "r"((a)[3]),                \
          "r"((b)[0]), "r"((b)[1]))

__global__ void __launch_bounds__(THREADS, 3)
bilin_hmma7(const float* __restrict__ X,   // [B, 32, 64]
            const float* __restrict__ W,   // [496, 64, 64]
            float* __restrict__ out)       // [B, 496, 64]
{
    extern __shared__ char smem[];
    const uint32_t sb  = smem_u32(smem);
    const int tid  = threadIdx.x;
    const int wid  = tid >> 5;
    const int lane = tid & 31;
    const int i    = blockIdx.y;
    const int b0   = blockIdx.x * MT;

    // ---- convert A = X[b0:b0+128, i, :] to bf16 hi/lo smem (persists) ----
    {
        const int m = tid;
        const float4* xr = (const float4*)(X + (size_t)(b0 + m) * FD + i * DDIM);
        char* ahp = smem + SM_AH + m * ROWB;
        char* alp = smem + SM_AL + m * ROWB;
        #pragma unroll
        for (int q = 0; q < 16; q++) {
            float4 v = xr[q];
            *(uint2*)(ahp + q * 8) = make_uint2(packbf(v.x, v.y), packbf(v.z, v.w));
            *(uint2*)(alp + q * 8) =
                make_uint2(packbf(v.x - bf_rt(v.x), v.y - bf_rt(v.y)),
                           packbf(v.z - bf_rt(v.z), v.w - bf_rt(v.w)));
        }
    }
    __syncthreads();

    const int pbase = i * (63 - i) / 2 - i - 1;   // p = pbase + j
    const int r16 = lane & 15;
    const int h16 = lane >> 4;
    const int kr  = lane & 15;
    const int nh  = lane >> 4;

    for (int j = i + 1; j < FFEAT; j++) {
        const int p = pbase + j;

        __syncthreads();   // prior iteration's ldmatrix reads of W done
        // ---- convert W_p -> bf16 hi/lo smem [k][n] (coalesced LDG.128) ----
        {
            const float4* wg = (const float4*)(W + (size_t)p * DDIM * DDIM);
            #pragma unroll
            for (int t = 0; t < 8; t++) {
                const int idx4 = tid + (t << 7);      // 0..1023
                const int k  = idx4 >> 4;
                const int e4 = (idx4 & 15) << 2;
                float4 v = wg[idx4];
                const uint32_t off = (uint32_t)(k * ROWB + e4 * 2);
                *(uint2*)(smem + SM_WH + off) =
                    make_uint2(packbf(v.x, v.y), packbf(v.z, v.w));
                *(uint2*)(smem + SM_WL + off) =
                    make_uint2(packbf(v.x - bf_rt(v.x), v.y - bf_rt(v.y)),
                               packbf(v.z - bf_rt(v.z), v.w - bf_rt(v.w)));
            }
        }
        __syncthreads();

        // ---- accumulate D = Xh Wh + Xl Wh + Xh Wl (streamed fragments) ----
        float acc[2][8][4];
        #pragma unroll
        for (int mt = 0; mt < 2; mt++)
            #pragma unroll
            for (int nt = 0; nt < 8; nt++)
                #pragma unroll
                for (int c = 0; c < 4; c++) acc[mt][nt][c] = 0.f;

        #pragma unroll
        for (int kt = 0; kt < 4; kt++) {
            uint32_t a_h[2][4], a_l[2][4];
            #pragma unroll
            for (int mt = 0; mt < 2; mt++) {
                const int m = wid * 32 + mt * 16 + r16;
                const uint32_t aoff = (uint32_t)(m * ROWB + kt * 32 + h16 * 16);
                LDSM_X4(a_h[mt], sb + SM_AH + aoff);
                LDSM_X4(a_l[mt], sb + SM_AL + aoff);
            }
            #pragma unroll
            for (int nb = 0; nb < 4; nb++) {
                uint32_t bh[4], bl[4];
                const uint32_t boff = (uint32_t)((kt * 16 + kr) * ROWB
                                                 + nb * 32 + nh * 16);
                LDSM_X4_T(bh, sb + SM_WH + boff);
                LDSM_X4_T(bl, sb + SM_WL + boff);
                #pragma unroll
                for (int mt = 0; mt < 2; mt++) {
                    MMA16816(acc[mt][2 * nb + 0], a_h[mt], bh + 0);
                    MMA16816(acc[mt][2 * nb + 1], a_h[mt], bh + 2);
                    MMA16816(acc[mt][2 * nb + 0], a_l[mt], bh + 0);
                    MMA16816(acc[mt][2 * nb + 1], a_l[mt], bh + 2);
                    MMA16816(acc[mt][2 * nb + 0], a_h[mt], bl + 0);
                    MMA16816(acc[mt][2 * nb + 1], a_h[mt], bl + 2);
                }
            }
        }

        // ---- epilogue: stage D half-tile in smem, then coalesced xj/out ----
        {
            char* stw = smem + SM_ST + wid * ST_WARP;
            const int tr = lane >> 2;
            const int tc = (lane & 3) * 2;
            const int r2 = lane >> 4;
            const int c4 = (lane & 15) * 4;
            #pragma unroll
            for (int mt = 0; mt < 2; mt++) {
                __syncwarp();
                #pragma unroll
                for (int nt = 0; nt < 8; nt++) {
                    *(float2*)(stw + (tr * STPITCH + nt * 8 + tc) * 4) =
                        make_float2(acc[mt][nt][0], acc[mt][nt][1]);
                    *(float2*)(stw + ((tr + 8) * STPITCH + nt * 8 + tc) * 4) =
                        make_float2(acc[mt][nt][2], acc[mt][nt][3]);
                }
                __syncwarp();
                #pragma unroll
                for (int s2 = 0; s2 < 8; s2++) {
                    const int r  = s2 * 2 + r2;
                    const int m0 = b0 + wid * 32 + mt * 16 + r;
                    float4 d  = *(const float4*)(stw + (r * STPITCH + c4) * 4);
                    float4 xv = *(const float4*)(X + (size_t)m0 * FD + j * DDIM + c4);
                    float4 o  = make_float4(d.x * xv.x, d.y * xv.y,
                                            d.z * xv.z, d.w * xv.w);
                    *(float4*)(out + ((size_t)m0 * P_PAIRS + p) * DDIM + c4) = o;
                }
            }
        }
    }
}

extern "C" void kernel_launch(void* const* d_in, const int* in_sizes, int n_in,
                              void* d_out, int out_size) {
    const float* X = (const float*)d_in[0];
    const float* W = (const float*)d_in[1];
    float* out = (float*)d_out;

    const int B = in_sizes[0] / FD;   // 4096

    cudaFuncSetAttribute(bilin_hmma7, cudaFuncAttributeMaxDynamicSharedMemorySize, SMEM_BYTES);

    dim3 grid(B / MT, FFEAT - 1);
    bilin_hmma7<<<grid, THREADS, SMEM_BYTES>>>(X, W, out);
}

// round 10
// speedup vs baseline: 1.3445x; 1.1724x over previous
#include <cuda_runtime.h>
#include <cuda_fp16.h>
#include <stdint.h>

#define FFEAT   32
#define DDIM    64
#define P_PAIRS 496
#define FD      (FFEAT * DDIM)   // 2048
#define MT      128
#define THREADS 128

// smem: A_hi[128][72]f16, A_lo[128][72]f16, W_hi[64][72]f16, staging[4][16][68]f32
#define APITCH 72
#define ROWB   (APITCH * 2)
#define SM_AH  0
#define SM_AL  (SM_AH + MT * ROWB)            // 18432
#define SM_WH  (SM_AL + MT * ROWB)            // 36864
#define SM_ST  (SM_WH + DDIM * ROWB)          // 46080
#define STPITCH 68
#define ST_WARP (16 * STPITCH * 4)             // 4352 B
#define SMEM_BYTES (SM_ST + 4 * ST_WARP)       // 63488  (3 CTAs: 190 KB <= 228)

static __device__ __forceinline__ uint32_t smem_u32(const void* p) {
    uint32_t a;
    asm("{ .reg .u64 t; cvta.to.shared.u64 t, %1; cvt.u32.u64 %0, t; }" : "=r"(a) : "l"(p));
    return a;
}
// pack two floats to f16x2 (first arg -> low half)
static __device__ __forceinline__ uint32_t packh(float lo_e, float hi_e) {
    uint32_t r;
    asm("cvt.rn.f16x2.f32 %0, %1, %2;" : "=r"(r) : "f"(hi_e), "f"(lo_e));
    return r;
}
static __device__ __forceinline__ float h_rt(float x) {
    return __half2float(__float2half_rn(x));
}

#define LDSM_X4(r, addr)                                                     \
    asm volatile("ldmatrix.sync.aligned.m8n8.x4.shared.b16 {%0,%1,%2,%3}, [%4];" \
        : "=r"((r)[0]), "=r"((r)[1]), "=r"((r)[2]), "=r"((r)[3]) : "r"(addr))
#define LDSM_X4_T(r, addr)                                                   \
    asm volatile("ldmatrix.sync.aligned.m8n8.x4.trans.shared.b16 {%0,%1,%2,%3}, [%4];" \
        : "=r"((r)[0]), "=r"((r)[1]), "=r"((r)[2]), "=r"((r)[3]) : "r"(addr))
#define MMA16816(d, a, b)                                                    \
    asm volatile("mma.sync.aligned.m16n8k16.row.col.f32.f16.f16.f32 "       \
        "{%0,%1,%2,%3},{%4,%5,%6,%7},{%8,%9},{%0,%1,%2,%3};"                 \
        : "+f"((d)[0]), "+f"((d)[1]), "+f"((d)[2]), "+f"((d)[3])             \
        : "r"((a)[0]), "r"((a)[1]), "r"((a)[2]), "r"((a)[3]),                \
          "r"((b)[0]), "r"((b)[1]))

__global__ void __launch_bounds__(THREADS, 3)
bilin_hmma8(const float* __restrict__ X,   // [B, 32, 64]
            const float* __restrict__ W,   // [496, 64, 64]
            float* __restrict__ out)       // [B, 496, 64]
{
    extern __shared__ char smem[];
    const uint32_t sb  = smem_u32(smem);
    const int tid  = threadIdx.x;
    const int wid  = tid >> 5;
    const int lane = tid & 31;
    const int i    = blockIdx.y;
    const int b0   = blockIdx.x * MT;

    // ---- convert A = X[b0:b0+128, i, :] to f16 hi/lo smem (persists) ----
    {
        const int m = tid;
        const float4* xr = (const float4*)(X + (size_t)(b0 + m) * FD + i * DDIM);
        char* ahp = smem + SM_AH + m * ROWB;
        char* alp = smem + SM_AL + m * ROWB;
        #pragma unroll
        for (int q = 0; q < 16; q++) {
            float4 v = xr[q];
            *(uint2*)(ahp + q * 8) = make_uint2(packh(v.x, v.y), packh(v.z, v.w));
            *(uint2*)(alp + q * 8) =
                make_uint2(packh(v.x - h_rt(v.x), v.y - h_rt(v.y)),
                           packh(v.z - h_rt(v.z), v.w - h_rt(v.w)));
        }
    }
    __syncthreads();

    const int pbase = i * (63 - i) / 2 - i - 1;   // p = pbase + j
    const int r16 = lane & 15;
    const int h16 = lane >> 4;
    const int kr  = lane & 15;
    const int nh  = lane >> 4;

    for (int j = i + 1; j < FFEAT; j++) {
        const int p = pbase + j;

        __syncthreads();   // prior iteration's ldmatrix reads of W done
        // ---- convert W_p -> f16 smem [k][n] (coalesced LDG.128) ----
        {
            const float4* wg = (const float4*)(W + (size_t)p * DDIM * DDIM);
            #pragma unroll
            for (int t = 0; t < 8; t++) {
                const int idx4 = tid + (t << 7);      // 0..1023
                const int k  = idx4 >> 4;
                const int e4 = (idx4 & 15) << 2;
                float4 v = wg[idx4];
                *(uint2*)(smem + SM_WH + (uint32_t)(k * ROWB + e4 * 2)) =
                    make_uint2(packh(v.x, v.y), packh(v.z, v.w));
            }
        }
        __syncthreads();

        // ---- accumulate D = Xh Wh + Xl Wh (streamed fragments) ----
        float acc[2][8][4];
        #pragma unroll
        for (int mt = 0; mt < 2; mt++)
            #pragma unroll
            for (int nt = 0; nt < 8; nt++)
                #pragma unroll
                for (int c = 0; c < 4; c++) acc[mt][nt][c] = 0.f;

        #pragma unroll
        for (int kt = 0; kt < 4; kt++) {
            uint32_t a_h[2][4], a_l[2][4];
            #pragma unroll
            for (int mt = 0; mt < 2; mt++) {
                const int m = wid * 32 + mt * 16 + r16;
                const uint32_t aoff = (uint32_t)(m * ROWB + kt * 32 + h16 * 16);
                LDSM_X4(a_h[mt], sb + SM_AH + aoff);
                LDSM_X4(a_l[mt], sb + SM_AL + aoff);
            }
            #pragma unroll
            for (int nb = 0; nb < 4; nb++) {
                uint32_t bh[4];
                const uint32_t boff = (uint32_t)((kt * 16 + kr) * ROWB
                                                 + nb * 32 + nh * 16);
                LDSM_X4_T(bh, sb + SM_WH + boff);
                #pragma unroll
                for (int mt = 0; mt < 2; mt++) {
                    MMA16816(acc[mt][2 * nb + 0], a_h[mt], bh + 0);
                    MMA16816(acc[mt][2 * nb + 1], a_h[mt], bh + 2);
                    MMA16816(acc[mt][2 * nb + 0], a_l[mt], bh + 0);
                    MMA16816(acc[mt][2 * nb + 1], a_l[mt], bh + 2);
                }
            }
        }

        // ---- epilogue: stage D half-tile in smem, then coalesced xj/out ----
        {
            char* stw = smem + SM_ST + wid * ST_WARP;
            const int tr = lane >> 2;
            const int tc = (lane & 3) * 2;
            const int r2 = lane >> 4;
            const int c4 = (lane & 15) * 4;
            #pragma unroll
            for (int mt = 0; mt < 2; mt++) {
                __syncwarp();
                #pragma unroll
                for (int nt = 0; nt < 8; nt++) {
                    *(float2*)(stw + (tr * STPITCH + nt * 8 + tc) * 4) =
                        make_float2(acc[mt][nt][0], acc[mt][nt][1]);
                    *(float2*)(stw + ((tr + 8) * STPITCH + nt * 8 + tc) * 4) =
                        make_float2(acc[mt][nt][2], acc[mt][nt][3]);
                }
                __syncwarp();
                #pragma unroll
                for (int s2 = 0; s2 < 8; s2++) {
                    const int r  = s2 * 2 + r2;
                    const int m0 = b0 + wid * 32 + mt * 16 + r;
                    float4 d  = *(const float4*)(stw + (r * STPITCH + c4) * 4);
                    float4 xv = *(const float4*)(X + (size_t)m0 * FD + j * DDIM + c4);
                    float4 o  = make_float4(d.x * xv.x, d.y * xv.y,
                                            d.z * xv.z, d.w * xv.w);
                    *(float4*)(out + ((size_t)m0 * P_PAIRS + p) * DDIM + c4) = o;
                }
            }
        }
    }
}

extern "C" void kernel_launch(void* const* d_in, const int* in_sizes, int n_in,
                              void* d_out, int out_size) {
    const float* X = (const float*)d_in[0];
    const float* W = (const float*)d_in[1];
    float* out = (float*)d_out;

    const int B = in_sizes[0] / FD;   // 4096

    cudaFuncSetAttribute(bilin_hmma8, cudaFuncAttributeMaxDynamicSharedMemorySize, SMEM_BYTES);

    dim3 grid(B / MT, FFEAT - 1);
    bilin_hmma8<<<grid, THREADS, SMEM_BYTES>>>(X, W, out);
}